// round 1
// baseline (speedup 1.0000x reference)
#include <cuda_runtime.h>
#include <math.h>

#define CN (256*1024)

// ---------------- device scratch (no allocations allowed) ----------------
__device__ float g_x[2*256*1024];     // LN1 out, (B,C,N)
__device__ float g_q[2*256*1024];     // q proj (B,C,N), unscaled
__device__ float g_vgrid[16*64*2];    // normalized kv coords per (b,g)
__device__ float g_kv[2*256*64];      // sampled kv (B,C,64)
__device__ float g_k[2*256*64];
__device__ float g_v[2*256*64];
__device__ float g_attn[2*1024*256];  // attention out (b,n,c)
__device__ float g_srcp[2*1024*256];  // src + out proj (b,n,c)
__device__ float g_src2[2*1024*256];  // LN2 out
__device__ float g_ffnh[2*1024*1024]; // ffn hidden

// ---------------- LayerNorm ----------------
__global__ void ln_kernel(const float* __restrict__ in, const float* __restrict__ gma,
                          const float* __restrict__ bta, float* __restrict__ out, int to_chw) {
    int row = blockIdx.x;            // b*1024 + n
    int t = threadIdx.x;             // channel
    float v = in[row*256 + t];
    float s = v, sq = v*v;
    #pragma unroll
    for (int o = 16; o; o >>= 1) {
        s  += __shfl_down_sync(0xffffffffu, s,  o);
        sq += __shfl_down_sync(0xffffffffu, sq, o);
    }
    __shared__ float ps[8], pq[8], mb[2];
    int w = t >> 5, l = t & 31;
    if (!l) { ps[w] = s; pq[w] = sq; }
    __syncthreads();
    if (!t) {
        float S = 0.f, Q = 0.f;
        #pragma unroll
        for (int i = 0; i < 8; i++) { S += ps[i]; Q += pq[i]; }
        float m = S * (1.f/256.f);
        float var = Q * (1.f/256.f) - m*m;
        mb[0] = m; mb[1] = rsqrtf(var + 1e-5f);
    }
    __syncthreads();
    float y = (v - mb[0]) * mb[1] * gma[t] + bta[t];
    if (to_chw) { int b = row >> 10, n = row & 1023; out[b*CN + t*1024 + n] = y; }
    else        out[row*256 + t] = y;
}

// ---------------- grouped 1x1 q projection ----------------
__global__ void qproj_kernel(const float* __restrict__ wq) {
    int bg = blockIdx.x; int b = bg >> 3, g = bg & 7;
    int n0 = blockIdx.y * 128;
    int t = threadIdx.x;
    __shared__ float wqs[1024], xs[32*128];
    for (int i = t; i < 1024; i += 256) wqs[i] = wq[g*1024 + i];
    for (int i = t; i < 4096; i += 256) {
        int c = i >> 7, nn = i & 127;
        xs[c*128 + nn] = g_x[b*CN + (g*32 + c)*1024 + n0 + nn];
    }
    __syncthreads();
    for (int i = t; i < 4096; i += 256) {
        int o = i >> 7, nn = i & 127;
        float a = 0.f;
        #pragma unroll
        for (int c = 0; c < 32; c++) a += xs[c*128 + nn] * wqs[o*32 + c];
        g_q[b*CN + (g*32 + o)*1024 + n0 + nn] = a;
    }
}

// ------- fused: depthwise conv(6x6,s4,p1) + GELU + offset proj + tanh + grid_sample -------
__global__ void offset_sample_kernel(const float* __restrict__ wdw, const float* __restrict__ bdw,
                                     const float* __restrict__ woff) {
    int bg = blockIdx.x; int b = bg >> 3, g = bg & 7;
    int t = threadIdx.x;
    __shared__ float wdws[1152], bdws[32], woffs[64], sg[2048], coords[128];
    for (int i = t; i < 1152; i += 256) wdws[i] = wdw[i];
    if (t < 32) bdws[t] = bdw[t];
    if (t < 64) woffs[t] = woff[t];
    __syncthreads();

    const float* qg = g_q + b*CN + g*32*1024;
    // depthwise conv + GELU -> sg[c][pos]
    for (int i = t; i < 2048; i += 256) {
        int c = i >> 6, pos = i & 63, oy = pos >> 3, ox = pos & 7;
        float a = 0.f;
        #pragma unroll
        for (int ky = 0; ky < 6; ky++) {
            int iy = oy*4 - 1 + ky;
            if ((unsigned)iy < 32u) {
                #pragma unroll
                for (int kx = 0; kx < 6; kx++) {
                    int ix = ox*4 - 1 + kx;
                    if ((unsigned)ix < 32u)
                        a += qg[c*1024 + iy*32 + ix] * wdws[c*36 + ky*6 + kx];
                }
            }
        }
        a += bdws[c];
        sg[c*64 + pos] = 0.5f * a * (1.f + erff(a * 0.70710678118654752f));
    }
    __syncthreads();
    // offsets -> normalized grid coords
    if (t < 128) {
        int pos = t >> 1, comp = t & 1;
        float s = 0.f;
        #pragma unroll
        for (int c = 0; c < 32; c++) s += sg[c*64 + pos] * woffs[comp*32 + c];
        float off = tanhf(s) * 4.f;
        float base = comp ? (float)(pos >> 3) : (float)(pos & 7);
        float gn = 2.f * (base + off) * (1.f/7.f) - 1.f;
        coords[pos*2 + comp] = gn;
        g_vgrid[bg*128 + pos*2 + comp] = gn;
    }
    __syncthreads();
    // bilinear grid_sample (zeros pad, align_corners=False)
    const float* xg = g_x + b*CN + g*32*1024;
    for (int i = t; i < 2048; i += 256) {
        int c = i >> 6, pos = i & 63;
        float xf = ((coords[pos*2 + 0] + 1.f)*32.f - 1.f)*0.5f;
        float yf = ((coords[pos*2 + 1] + 1.f)*32.f - 1.f)*0.5f;
        float x0f = floorf(xf), y0f = floorf(yf);
        int x0 = (int)x0f, y0 = (int)y0f;
        float wx1 = xf - x0f, wx0 = 1.f - wx1, wy1 = yf - y0f, wy0 = 1.f - wy1;
        float acc = 0.f;
        #pragma unroll
        for (int dy = 0; dy < 2; dy++) {
            int iy = y0 + dy;
            if ((unsigned)iy >= 32u) continue;
            float wy = dy ? wy1 : wy0;
            #pragma unroll
            for (int dx = 0; dx < 2; dx++) {
                int ix = x0 + dx;
                if ((unsigned)ix >= 32u) continue;
                float wxx = dx ? wx1 : wx0;
                acc += xg[c*1024 + iy*32 + ix] * wxx * wy;
            }
        }
        g_kv[(b*256 + g*32 + c)*64 + pos] = acc;
    }
}

// ---------------- grouped 1x1 k,v projections ----------------
__global__ void kvproj_kernel(const float* __restrict__ wk, const float* __restrict__ wv) {
    int bg = blockIdx.x; int b = bg >> 3, g = bg & 7; int t = threadIdx.x;
    __shared__ float kvs[2048], wks[1024], wvs[1024];
    for (int i = t; i < 1024; i += 256) { wks[i] = wk[g*1024 + i]; wvs[i] = wv[g*1024 + i]; }
    for (int i = t; i < 2048; i += 256) kvs[i] = g_kv[(b*256 + g*32)*64 + i];
    __syncthreads();
    for (int i = t; i < 2048; i += 256) {
        int o = i >> 6, j = i & 63;
        float ak = 0.f, av = 0.f;
        #pragma unroll
        for (int c = 0; c < 32; c++) {
            float f = kvs[c*64 + j];
            ak += f * wks[o*32 + c];
            av += f * wvs[o*32 + c];
        }
        g_k[(b*256 + g*32 + o)*64 + j] = ak;
        g_v[(b*256 + g*32 + o)*64 + j] = av;
    }
}

// -------- fused attention: sim + CPB bias MLP + softmax + attn@v --------
__global__ __launch_bounds__(256) void attn_kernel(
        const float* __restrict__ w0, const float* __restrict__ b0,
        const float* __restrict__ w1, const float* __restrict__ b1,
        const float* __restrict__ w2, const float* __restrict__ b2p) {
    int bh = blockIdx.y; int b = bh >> 3, h = bh & 7;
    int i0 = blockIdx.x * 32;
    int t = threadIdx.x;

    __shared__ __align__(16) float W1s[4096];
    __shared__ __align__(16) float b1s[64];
    __shared__ float W0s[128], b0s[64], w2s[64];
    __shared__ float ks[64*33], vs[64*33], qs[32*33], ck[128], logits[2048];

    for (int i = t; i < 4096; i += 256) W1s[i] = w1[i];
    if (t < 128) W0s[t] = w0[t];
    if (t < 64) { b0s[t] = b0[t]; b1s[t] = b1[t]; w2s[t] = w2[t]; }
    if (t < 128) ck[t] = g_vgrid[bh*128 + t];
    for (int i = t; i < 2048; i += 256) {
        int d = i >> 6, j = i & 63;
        ks[j*33 + d] = g_k[(b*256 + h*32 + d)*64 + j];
        vs[j*33 + d] = g_v[(b*256 + h*32 + d)*64 + j];
    }
    for (int i = t; i < 1024; i += 256) {
        int d = i >> 5, ii = i & 31;
        qs[ii*33 + d] = g_q[b*CN + (h*32 + d)*1024 + i0 + ii] * 0.17677669529663687f; // 32^-0.5
    }
    __syncthreads();

    float bias2 = b2p[0];
    const float4* W1r = (const float4*)W1s;
    const float4* b1r = (const float4*)b1s;

    for (int p = 0; p < 8; p++) {
        int pr = p*256 + t;
        int ii = pr >> 6, j = pr & 63;
        int gi = i0 + ii;
        float px = 2.f * (float)(gi & 31) * (1.f/31.f) - 1.f;
        float py = 2.f * (float)(gi >> 5) * (1.f/31.f) - 1.f;
        float dx = px - ck[j*2], dy = py - ck[j*2 + 1];
        float fx = copysignf(log1pf(fabsf(dx)), dx);
        float fy = copysignf(log1pf(fabsf(dy)), dy);

        float h1[64];
        #pragma unroll
        for (int u = 0; u < 64; u++)
            h1[u] = fmaxf(fx*W0s[u] + fy*W0s[64 + u] + b0s[u], 0.f);

        float bias = bias2;
        for (int ob = 0; ob < 16; ob++) {
            float4 acc = b1r[ob];
            #pragma unroll
            for (int u = 0; u < 64; u++) {
                float4 wv4 = W1r[u*16 + ob];   // broadcast across warp
                acc.x += h1[u]*wv4.x; acc.y += h1[u]*wv4.y;
                acc.z += h1[u]*wv4.z; acc.w += h1[u]*wv4.w;
            }
            bias += fmaxf(acc.x, 0.f)*w2s[ob*4 + 0]
                  + fmaxf(acc.y, 0.f)*w2s[ob*4 + 1]
                  + fmaxf(acc.z, 0.f)*w2s[ob*4 + 2]
                  + fmaxf(acc.w, 0.f)*w2s[ob*4 + 3];
        }

        float s = 0.f;
        #pragma unroll
        for (int d = 0; d < 32; d++) s += qs[ii*33 + d] * ks[j*33 + d];
        logits[ii*64 + j] = s + bias;
    }
    __syncthreads();

    // softmax over j=64 per row: 8 warps x 4 rows
    int w = t >> 5, l = t & 31;
    for (int rr = 0; rr < 4; rr++) {
        int row = w*4 + rr;
        float l0 = logits[row*64 + l], l1 = logits[row*64 + 32 + l];
        float m = fmaxf(l0, l1);
        #pragma unroll
        for (int o = 16; o; o >>= 1) m = fmaxf(m, __shfl_xor_sync(0xffffffffu, m, o));
        float e0 = __expf(l0 - m), e1 = __expf(l1 - m);
        float ss = e0 + e1;
        #pragma unroll
        for (int o = 16; o; o >>= 1) ss += __shfl_xor_sync(0xffffffffu, ss, o);
        float inv = 1.f / ss;
        logits[row*64 + l] = e0*inv;
        logits[row*64 + 32 + l] = e1*inv;
    }
    __syncthreads();

    for (int r = 0; r < 4; r++) {
        int idx = t + r*256;
        int ii = idx >> 5, d = idx & 31;
        float acc = 0.f;
        #pragma unroll
        for (int j = 0; j < 64; j++) acc += logits[ii*64 + j] * vs[j*33 + d];
        g_attn[(b*1024 + i0 + ii)*256 + h*32 + d] = acc;
    }
}

// ---------------- tiled fp32 GEMM with fused epilogue ----------------
// A: MxK row-major. BT=false: B is KxN. BT=true: B is NxK (C = A @ B^T).
// EPI 0: C = acc + bias[col] + res[row,col] ; EPI 1: C = relu(acc + bias[col])
template<bool BT, int EPI>
__global__ __launch_bounds__(256) void gemm_kernel(
        const float* __restrict__ A, const float* __restrict__ B,
        const float* __restrict__ bias, const float* __restrict__ res,
        float* __restrict__ C, int M, int N, int K) {
    const int m0 = blockIdx.y * 64, n0 = blockIdx.x * 64;
    __shared__ __align__(16) float As[16*68];
    __shared__ __align__(16) float Bs[16*68];
    int t = threadIdx.x;
    int ty = t >> 4, tx = t & 15;
    float acc[4][4] = {};
    for (int k0 = 0; k0 < K; k0 += 16) {
        {
            int r = t >> 2, kk = (t & 3) * 4;
            float4 v = *(const float4*)&A[(m0 + r)*K + k0 + kk];
            As[(kk+0)*68 + r] = v.x; As[(kk+1)*68 + r] = v.y;
            As[(kk+2)*68 + r] = v.z; As[(kk+3)*68 + r] = v.w;
        }
        if (BT) {
            int r = t >> 2, kk = (t & 3) * 4;
            float4 v = *(const float4*)&B[(n0 + r)*K + k0 + kk];
            Bs[(kk+0)*68 + r] = v.x; Bs[(kk+1)*68 + r] = v.y;
            Bs[(kk+2)*68 + r] = v.z; Bs[(kk+3)*68 + r] = v.w;
        } else {
            int r = t >> 4, cc = (t & 15) * 4;
            float4 v = *(const float4*)&B[(k0 + r)*N + n0 + cc];
            Bs[r*68 + cc + 0] = v.x; Bs[r*68 + cc + 1] = v.y;
            Bs[r*68 + cc + 2] = v.z; Bs[r*68 + cc + 3] = v.w;
        }
        __syncthreads();
        #pragma unroll
        for (int k = 0; k < 16; k++) {
            float4 a  = *(const float4*)&As[k*68 + ty*4];
            float4 bb = *(const float4*)&Bs[k*68 + tx*4];
            float av[4] = {a.x, a.y, a.z, a.w};
            float bv[4] = {bb.x, bb.y, bb.z, bb.w};
            #pragma unroll
            for (int i = 0; i < 4; i++)
                #pragma unroll
                for (int j = 0; j < 4; j++) acc[i][j] += av[i]*bv[j];
        }
        __syncthreads();
    }
    #pragma unroll
    for (int i = 0; i < 4; i++) {
        int row = m0 + ty*4 + i;
        #pragma unroll
        for (int j = 0; j < 4; j++) {
            int col = n0 + tx*4 + j;
            float v = acc[i][j] + bias[col];
            if (EPI == 1) v = fmaxf(v, 0.f);
            else          v += res[row*N + col];
            C[row*N + col] = v;
        }
    }
}

// ---------------- launcher ----------------
extern "C" void kernel_launch(void* const* d_in, const int* in_sizes, int n_in,
                              void* d_out, int out_size) {
    const float* src     = (const float*)d_in[0];
    const float* norm1_g = (const float*)d_in[1];
    const float* norm1_b = (const float*)d_in[2];
    const float* wq      = (const float*)d_in[3];
    const float* wdw     = (const float*)d_in[4];
    const float* bdw     = (const float*)d_in[5];
    const float* woff    = (const float*)d_in[6];
    const float* wk      = (const float*)d_in[7];
    const float* wv      = (const float*)d_in[8];
    const float* cpb_w0  = (const float*)d_in[9];
    const float* cpb_b0  = (const float*)d_in[10];
    const float* cpb_w1  = (const float*)d_in[11];
    const float* cpb_b1  = (const float*)d_in[12];
    const float* cpb_w2  = (const float*)d_in[13];
    const float* cpb_b2  = (const float*)d_in[14];
    const float* wout    = (const float*)d_in[15];
    const float* bout    = (const float*)d_in[16];
    const float* norm2_g = (const float*)d_in[17];
    const float* norm2_b = (const float*)d_in[18];
    const float* ffn_w1  = (const float*)d_in[19];
    const float* ffn_b1  = (const float*)d_in[20];
    const float* ffn_w2  = (const float*)d_in[21];
    const float* ffn_b2  = (const float*)d_in[22];

    void *p_x, *p_attn, *p_srcp, *p_src2, *p_ffnh;
    cudaGetSymbolAddress(&p_x,    g_x);
    cudaGetSymbolAddress(&p_attn, g_attn);
    cudaGetSymbolAddress(&p_srcp, g_srcp);
    cudaGetSymbolAddress(&p_src2, g_src2);
    cudaGetSymbolAddress(&p_ffnh, g_ffnh);

    ln_kernel<<<2048, 256>>>(src, norm1_g, norm1_b, (float*)p_x, 1);
    qproj_kernel<<<dim3(16, 8), 256>>>(wq);
    offset_sample_kernel<<<16, 256>>>(wdw, bdw, woff);
    kvproj_kernel<<<16, 256>>>(wk, wv);
    attn_kernel<<<dim3(32, 16), 256>>>(cpb_w0, cpb_b0, cpb_w1, cpb_b1, cpb_w2, cpb_b2);
    gemm_kernel<true, 0><<<dim3(4, 32), 256>>>((const float*)p_attn, wout, bout, src,
                                               (float*)p_srcp, 2048, 256, 256);
    ln_kernel<<<2048, 256>>>((const float*)p_srcp, norm2_g, norm2_b, (float*)p_src2, 0);
    gemm_kernel<false, 1><<<dim3(16, 32), 256>>>((const float*)p_src2, ffn_w1, ffn_b1, nullptr,
                                                 (float*)p_ffnh, 2048, 1024, 256);
    gemm_kernel<false, 0><<<dim3(4, 32), 256>>>((const float*)p_ffnh, ffn_w2, ffn_b2,
                                                (const float*)p_srcp, (float*)d_out,
                                                2048, 256, 1024);
}

// round 2
// speedup vs baseline: 2.3439x; 2.3439x over previous
#include <cuda_runtime.h>
#include <cuda_bf16.h>
#include <math.h>

#define CN (256*1024)

// ---------------- device scratch ----------------
__device__ float g_x[2*256*1024];     // LN1 out, (B,C,N)
__device__ float g_q[2*256*1024];     // q proj (B,C,N), unscaled
__device__ float g_vgrid[16*64*2];    // normalized kv coords per (b,g)
__device__ float g_k[2*256*64];
__device__ float g_v[2*256*64];
__device__ float g_attn[2*1024*256];  // attention out (b,n,c)
__device__ float g_srcp[2*1024*256];  // src + out proj (b,n,c)
__device__ float g_src2[2*1024*256];  // LN2 out
__device__ float g_ffnh[2*1024*1024]; // ffn hidden

__device__ __forceinline__ unsigned pack_bf16(float lo, float hi) {
    __nv_bfloat162 v = __floats2bfloat162_rn(lo, hi);
    return *(unsigned*)&v;
}

__device__ __forceinline__ void mma_bf16(float& c0, float& c1, float& c2, float& c3,
        unsigned a0, unsigned a1, unsigned a2, unsigned a3,
        unsigned b0, unsigned b1) {
    asm volatile("mma.sync.aligned.m16n8k16.row.col.f32.bf16.bf16.f32 "
        "{%0,%1,%2,%3}, {%4,%5,%6,%7}, {%8,%9}, {%0,%1,%2,%3};"
        : "+f"(c0), "+f"(c1), "+f"(c2), "+f"(c3)
        : "r"(a0), "r"(a1), "r"(a2), "r"(a3), "r"(b0), "r"(b1));
}

// ---------------- LayerNorm ----------------
__global__ void ln_kernel(const float* __restrict__ in, const float* __restrict__ gma,
                          const float* __restrict__ bta, float* __restrict__ out, int to_chw) {
    int row = blockIdx.x;
    int t = threadIdx.x;
    float v = in[row*256 + t];
    float s = v, sq = v*v;
    #pragma unroll
    for (int o = 16; o; o >>= 1) {
        s  += __shfl_down_sync(0xffffffffu, s,  o);
        sq += __shfl_down_sync(0xffffffffu, sq, o);
    }
    __shared__ float ps[8], pq[8], mb[2];
    int w = t >> 5, l = t & 31;
    if (!l) { ps[w] = s; pq[w] = sq; }
    __syncthreads();
    if (!t) {
        float S = 0.f, Q = 0.f;
        #pragma unroll
        for (int i = 0; i < 8; i++) { S += ps[i]; Q += pq[i]; }
        float m = S * (1.f/256.f);
        float var = Q * (1.f/256.f) - m*m;
        mb[0] = m; mb[1] = rsqrtf(var + 1e-5f);
    }
    __syncthreads();
    float y = (v - mb[0]) * mb[1] * gma[t] + bta[t];
    if (to_chw) { int b = row >> 10, n = row & 1023; out[b*CN + t*1024 + n] = y; }
    else        out[row*256 + t] = y;
}

// ---------------- grouped 1x1 q projection ----------------
__global__ void qproj_kernel(const float* __restrict__ wq) {
    int bg = blockIdx.x; int b = bg >> 3, g = bg & 7;
    int n0 = blockIdx.y * 128;
    int t = threadIdx.x;
    __shared__ float wqs[1024], xs[32*128];
    for (int i = t; i < 1024; i += 256) wqs[i] = wq[g*1024 + i];
    for (int i = t; i < 4096; i += 256) {
        int c = i >> 7, nn = i & 127;
        xs[c*128 + nn] = g_x[b*CN + (g*32 + c)*1024 + n0 + nn];
    }
    __syncthreads();
    for (int i = t; i < 4096; i += 256) {
        int o = i >> 7, nn = i & 127;
        float a = 0.f;
        #pragma unroll
        for (int c = 0; c < 32; c++) a += xs[c*128 + nn] * wqs[o*32 + c];
        g_q[b*CN + (g*32 + o)*1024 + n0 + nn] = a;
    }
}

// --- fused: depthwise conv + GELU + offset proj + tanh + grid_sample + k/v proj ---
__global__ void offset_sample_kv_kernel(const float* __restrict__ wdw, const float* __restrict__ bdw,
                                        const float* __restrict__ woff,
                                        const float* __restrict__ wk, const float* __restrict__ wv) {
    int bg = blockIdx.x; int b = bg >> 3, g = bg & 7;
    int t = threadIdx.x;
    __shared__ float wdws[1152], bdws[32], woffs[64], sg[2048], coords[128];
    __shared__ float samp[2048], wks[1024], wvs[1024];
    for (int i = t; i < 1152; i += 256) wdws[i] = wdw[i];
    if (t < 32) bdws[t] = bdw[t];
    if (t < 64) woffs[t] = woff[t];
    for (int i = t; i < 1024; i += 256) { wks[i] = wk[g*1024 + i]; wvs[i] = wv[g*1024 + i]; }
    __syncthreads();

    const float* qg = g_q + b*CN + g*32*1024;
    for (int i = t; i < 2048; i += 256) {
        int c = i >> 6, pos = i & 63, oy = pos >> 3, ox = pos & 7;
        float a = 0.f;
        #pragma unroll
        for (int ky = 0; ky < 6; ky++) {
            int iy = oy*4 - 1 + ky;
            if ((unsigned)iy < 32u) {
                #pragma unroll
                for (int kx = 0; kx < 6; kx++) {
                    int ix = ox*4 - 1 + kx;
                    if ((unsigned)ix < 32u)
                        a += qg[c*1024 + iy*32 + ix] * wdws[c*36 + ky*6 + kx];
                }
            }
        }
        a += bdws[c];
        sg[c*64 + pos] = 0.5f * a * (1.f + erff(a * 0.70710678118654752f));
    }
    __syncthreads();
    if (t < 128) {
        int pos = t >> 1, comp = t & 1;
        float s = 0.f;
        #pragma unroll
        for (int c = 0; c < 32; c++) s += sg[c*64 + pos] * woffs[comp*32 + c];
        float off = tanhf(s) * 4.f;
        float base = comp ? (float)(pos >> 3) : (float)(pos & 7);
        float gn = 2.f * (base + off) * (1.f/7.f) - 1.f;
        coords[pos*2 + comp] = gn;
        g_vgrid[bg*128 + pos*2 + comp] = gn;
    }
    __syncthreads();
    const float* xg = g_x + b*CN + g*32*1024;
    for (int i = t; i < 2048; i += 256) {
        int c = i >> 6, pos = i & 63;
        float xf = ((coords[pos*2 + 0] + 1.f)*32.f - 1.f)*0.5f;
        float yf = ((coords[pos*2 + 1] + 1.f)*32.f - 1.f)*0.5f;
        float x0f = floorf(xf), y0f = floorf(yf);
        int x0 = (int)x0f, y0 = (int)y0f;
        float wx1 = xf - x0f, wx0 = 1.f - wx1, wy1 = yf - y0f, wy0 = 1.f - wy1;
        float acc = 0.f;
        #pragma unroll
        for (int dy = 0; dy < 2; dy++) {
            int iy = y0 + dy;
            if ((unsigned)iy >= 32u) continue;
            float wy = dy ? wy1 : wy0;
            #pragma unroll
            for (int dx = 0; dx < 2; dx++) {
                int ix = x0 + dx;
                if ((unsigned)ix >= 32u) continue;
                float wxx = dx ? wx1 : wx0;
                acc += xg[c*1024 + iy*32 + ix] * wxx * wy;
            }
        }
        samp[c*64 + pos] = acc;
    }
    __syncthreads();
    for (int i = t; i < 2048; i += 256) {
        int o = i >> 6, j = i & 63;
        float ak = 0.f, av = 0.f;
        #pragma unroll
        for (int c = 0; c < 32; c++) {
            float f = samp[c*64 + j];
            ak += f * wks[o*32 + c];
            av += f * wvs[o*32 + c];
        }
        g_k[(b*256 + g*32 + o)*64 + j] = ak;
        g_v[(b*256 + g*32 + o)*64 + j] = av;
    }
}

// -------- fused attention: sim + CPB bias MLP (bf16 HMMA) + softmax + attn@v --------
__global__ __launch_bounds__(256) void attn_kernel(
        const float* __restrict__ w0, const float* __restrict__ b0p,
        const float* __restrict__ w1, const float* __restrict__ b1p,
        const float* __restrict__ w2, const float* __restrict__ b2p) {
    int bh = blockIdx.y; int b = bh >> 3, h = bh & 7;
    int i0 = blockIdx.x * 32;
    int t = threadIdx.x, w = t >> 5, l = t & 31, g = l >> 2, tig = l & 3;

    __shared__ float ks[64*33], vs[64*33], qs[32*33];
    __shared__ float ck[128], W0s[128], b0s[64], b1s[64], w2s[64];
    __shared__ unsigned W1b[2048];          // pre-packed bf16x2 B fragments
    __shared__ float fxs[2048], fys[64], logits[2048];

    if (t < 128) { W0s[t] = w0[t]; ck[t] = g_vgrid[bh*128 + t]; }
    if (t < 64) { b0s[t] = b0p[t]; b1s[t] = b1p[t]; w2s[t] = w2[t]; }
    for (int i = t; i < 2048; i += 256) {
        int d = i >> 6, j = i & 63;
        ks[j*33 + d] = g_k[(b*256 + h*32 + d)*64 + j];
        vs[j*33 + d] = g_v[(b*256 + h*32 + d)*64 + j];
    }
    for (int i = t; i < 1024; i += 256) {
        int d = i >> 5, ii = i & 31;
        qs[ii*33 + d] = g_q[b*CN + (h*32 + d)*1024 + i0 + ii] * 0.17677669529663687f;
    }
    // pack W1 -> per-lane bf16x2 B fragments: [kt][nt][reg][lane]
    for (int i = t; i < 2048; i += 256) {
        int kt = i >> 9, rem = i & 511;
        int nt = rem >> 6, reg = (rem >> 5) & 1, lane = rem & 31;
        int gg = lane >> 2, ti = lane & 3;
        int k = kt*16 + reg*8 + ti*2;
        int col = nt*8 + gg;
        W1b[i] = pack_bf16(w1[k*64 + col], w1[(k+1)*64 + col]);
    }
    __syncthreads();

    // precompute CPB log-features
    float py = 2.f * (float)blockIdx.x * (1.f/31.f) - 1.f;
    if (t < 64) {
        float dy = py - ck[2*t + 1];
        fys[t] = copysignf(log1pf(fabsf(dy)), dy);
    }
    for (int i = t; i < 2048; i += 256) {
        int ii = i >> 6, j = i & 63;
        float px = 2.f * (float)ii * (1.f/31.f) - 1.f;
        float dx = px - ck[2*j];
        fxs[i] = copysignf(log1pf(fabsf(dx)), dx);
    }
    __syncthreads();

    float b2v = b2p[0];
    int pbase = w*256;
    for (int mt = 0; mt < 16; mt++) {
        int p0 = pbase + mt*16 + g;   // row g
        int p1 = p0 + 8;              // row g+8
        int ii0 = p0 >> 6, j0 = p0 & 63;
        int ii1 = p1 >> 6, j1 = p1 & 63;
        float fx0 = fxs[p0], fy0 = fys[j0];
        float fx1 = fxs[p1], fy1 = fys[j1];

        unsigned a[4][4];
        #pragma unroll
        for (int kt = 0; kt < 4; kt++) {
            int d0 = kt*16 + 2*tig;
            int d2 = d0 + 8;
            float h00 = fmaxf(fx0*W0s[d0]   + fy0*W0s[64+d0]   + b0s[d0],   0.f);
            float h01 = fmaxf(fx0*W0s[d0+1] + fy0*W0s[64+d0+1] + b0s[d0+1], 0.f);
            float h02 = fmaxf(fx0*W0s[d2]   + fy0*W0s[64+d2]   + b0s[d2],   0.f);
            float h03 = fmaxf(fx0*W0s[d2+1] + fy0*W0s[64+d2+1] + b0s[d2+1], 0.f);
            float h10 = fmaxf(fx1*W0s[d0]   + fy1*W0s[64+d0]   + b0s[d0],   0.f);
            float h11 = fmaxf(fx1*W0s[d0+1] + fy1*W0s[64+d0+1] + b0s[d0+1], 0.f);
            float h12 = fmaxf(fx1*W0s[d2]   + fy1*W0s[64+d2]   + b0s[d2],   0.f);
            float h13 = fmaxf(fx1*W0s[d2+1] + fy1*W0s[64+d2+1] + b0s[d2+1], 0.f);
            a[kt][0] = pack_bf16(h00, h01);
            a[kt][1] = pack_bf16(h10, h11);
            a[kt][2] = pack_bf16(h02, h03);
            a[kt][3] = pack_bf16(h12, h13);
        }

        float acc0 = 0.f, acc1 = 0.f;
        #pragma unroll
        for (int nt = 0; nt < 8; nt++) {
            float c0 = 0.f, c1 = 0.f, c2 = 0.f, c3 = 0.f;
            #pragma unroll
            for (int kt = 0; kt < 4; kt++) {
                unsigned br0 = W1b[((kt*8 + nt)*2 + 0)*32 + l];
                unsigned br1 = W1b[((kt*8 + nt)*2 + 1)*32 + l];
                mma_bf16(c0, c1, c2, c3, a[kt][0], a[kt][1], a[kt][2], a[kt][3], br0, br1);
            }
            int col0 = nt*8 + 2*tig;
            acc0 += fmaxf(c0 + b1s[col0],   0.f)*w2s[col0]
                  + fmaxf(c1 + b1s[col0+1], 0.f)*w2s[col0+1];
            acc1 += fmaxf(c2 + b1s[col0],   0.f)*w2s[col0]
                  + fmaxf(c3 + b1s[col0+1], 0.f)*w2s[col0+1];
        }
        // q.k partial sums (each quad-lane covers 8 dims), fused into same reduction
        #pragma unroll
        for (int dd = 0; dd < 8; dd++) {
            int d = tig*8 + dd;
            acc0 += qs[ii0*33 + d]*ks[j0*33 + d];
            acc1 += qs[ii1*33 + d]*ks[j1*33 + d];
        }
        acc0 += __shfl_xor_sync(0xffffffffu, acc0, 1);
        acc0 += __shfl_xor_sync(0xffffffffu, acc0, 2);
        acc1 += __shfl_xor_sync(0xffffffffu, acc1, 1);
        acc1 += __shfl_xor_sync(0xffffffffu, acc1, 2);
        if (tig == 0) { logits[p0] = acc0 + b2v; logits[p1] = acc1 + b2v; }
    }
    __syncthreads();

    // softmax over j=64 per row
    for (int rr = 0; rr < 4; rr++) {
        int row = w*4 + rr;
        float l0 = logits[row*64 + l], l1 = logits[row*64 + 32 + l];
        float m = fmaxf(l0, l1);
        #pragma unroll
        for (int o = 16; o; o >>= 1) m = fmaxf(m, __shfl_xor_sync(0xffffffffu, m, o));
        float e0 = __expf(l0 - m), e1 = __expf(l1 - m);
        float ss = e0 + e1;
        #pragma unroll
        for (int o = 16; o; o >>= 1) ss += __shfl_xor_sync(0xffffffffu, ss, o);
        float inv = 1.f / ss;
        logits[row*64 + l] = e0*inv;
        logits[row*64 + 32 + l] = e1*inv;
    }
    __syncthreads();

    for (int r = 0; r < 4; r++) {
        int idx = t + r*256;
        int ii = idx >> 5, d = idx & 31;
        float acc = 0.f;
        #pragma unroll
        for (int j = 0; j < 64; j++) acc += logits[ii*64 + j] * vs[j*33 + d];
        g_attn[(b*1024 + i0 + ii)*256 + h*32 + d] = acc;
    }
}

// ---------------- tiled fp32 GEMM with fused epilogue ----------------
template<bool BT, int EPI>
__global__ __launch_bounds__(256) void gemm_kernel(
        const float* __restrict__ A, const float* __restrict__ B,
        const float* __restrict__ bias, const float* __restrict__ res,
        float* __restrict__ C, int M, int N, int K) {
    const int m0 = blockIdx.y * 64, n0 = blockIdx.x * 64;
    __shared__ __align__(16) float As[16*68];
    __shared__ __align__(16) float Bs[16*68];
    int t = threadIdx.x;
    int ty = t >> 4, tx = t & 15;
    float acc[4][4] = {};
    for (int k0 = 0; k0 < K; k0 += 16) {
        {
            int r = t >> 2, kk = (t & 3) * 4;
            float4 v = *(const float4*)&A[(m0 + r)*K + k0 + kk];
            As[(kk+0)*68 + r] = v.x; As[(kk+1)*68 + r] = v.y;
            As[(kk+2)*68 + r] = v.z; As[(kk+3)*68 + r] = v.w;
        }
        if (BT) {
            int r = t >> 2, kk = (t & 3) * 4;
            float4 v = *(const float4*)&B[(n0 + r)*K + k0 + kk];
            Bs[(kk+0)*68 + r] = v.x; Bs[(kk+1)*68 + r] = v.y;
            Bs[(kk+2)*68 + r] = v.z; Bs[(kk+3)*68 + r] = v.w;
        } else {
            int r = t >> 4, cc = (t & 15) * 4;
            float4 v = *(const float4*)&B[(k0 + r)*N + n0 + cc];
            Bs[r*68 + cc + 0] = v.x; Bs[r*68 + cc + 1] = v.y;
            Bs[r*68 + cc + 2] = v.z; Bs[r*68 + cc + 3] = v.w;
        }
        __syncthreads();
        #pragma unroll
        for (int k = 0; k < 16; k++) {
            float4 a  = *(const float4*)&As[k*68 + ty*4];
            float4 bb = *(const float4*)&Bs[k*68 + tx*4];
            float av[4] = {a.x, a.y, a.z, a.w};
            float bv[4] = {bb.x, bb.y, bb.z, bb.w};
            #pragma unroll
            for (int i = 0; i < 4; i++)
                #pragma unroll
                for (int j = 0; j < 4; j++) acc[i][j] += av[i]*bv[j];
        }
        __syncthreads();
    }
    #pragma unroll
    for (int i = 0; i < 4; i++) {
        int row = m0 + ty*4 + i;
        #pragma unroll
        for (int j = 0; j < 4; j++) {
            int col = n0 + tx*4 + j;
            float v = acc[i][j] + bias[col];
            if (EPI == 1) v = fmaxf(v, 0.f);
            else          v += res[row*N + col];
            C[row*N + col] = v;
        }
    }
}

// ---------------- launcher ----------------
extern "C" void kernel_launch(void* const* d_in, const int* in_sizes, int n_in,
                              void* d_out, int out_size) {
    const float* src     = (const float*)d_in[0];
    const float* norm1_g = (const float*)d_in[1];
    const float* norm1_b = (const float*)d_in[2];
    const float* wq      = (const float*)d_in[3];
    const float* wdw     = (const float*)d_in[4];
    const float* bdw     = (const float*)d_in[5];
    const float* woff    = (const float*)d_in[6];
    const float* wk      = (const float*)d_in[7];
    const float* wv      = (const float*)d_in[8];
    const float* cpb_w0  = (const float*)d_in[9];
    const float* cpb_b0  = (const float*)d_in[10];
    const float* cpb_w1  = (const float*)d_in[11];
    const float* cpb_b1  = (const float*)d_in[12];
    const float* cpb_w2  = (const float*)d_in[13];
    const float* cpb_b2  = (const float*)d_in[14];
    const float* wout    = (const float*)d_in[15];
    const float* bout    = (const float*)d_in[16];
    const float* norm2_g = (const float*)d_in[17];
    const float* norm2_b = (const float*)d_in[18];
    const float* ffn_w1  = (const float*)d_in[19];
    const float* ffn_b1  = (const float*)d_in[20];
    const float* ffn_w2  = (const float*)d_in[21];
    const float* ffn_b2  = (const float*)d_in[22];

    void *p_x, *p_attn, *p_srcp, *p_src2, *p_ffnh;
    cudaGetSymbolAddress(&p_x,    g_x);
    cudaGetSymbolAddress(&p_attn, g_attn);
    cudaGetSymbolAddress(&p_srcp, g_srcp);
    cudaGetSymbolAddress(&p_src2, g_src2);
    cudaGetSymbolAddress(&p_ffnh, g_ffnh);

    ln_kernel<<<2048, 256>>>(src, norm1_g, norm1_b, (float*)p_x, 1);
    qproj_kernel<<<dim3(16, 8), 256>>>(wq);
    offset_sample_kv_kernel<<<16, 256>>>(wdw, bdw, woff, wk, wv);
    attn_kernel<<<dim3(32, 16), 256>>>(cpb_w0, cpb_b0, cpb_w1, cpb_b1, cpb_w2, cpb_b2);
    gemm_kernel<true, 0><<<dim3(4, 32), 256>>>((const float*)p_attn, wout, bout, src,
                                               (float*)p_srcp, 2048, 256, 256);
    ln_kernel<<<2048, 256>>>((const float*)p_srcp, norm2_g, norm2_b, (float*)p_src2, 0);
    gemm_kernel<false, 1><<<dim3(16, 32), 256>>>((const float*)p_src2, ffn_w1, ffn_b1, nullptr,
                                                 (float*)p_ffnh, 2048, 1024, 256);
    gemm_kernel<false, 0><<<dim3(4, 32), 256>>>((const float*)p_ffnh, ffn_w2, ffn_b2,
                                                (const float*)p_srcp, (float*)d_out,
                                                2048, 256, 1024);
}

// round 3
// speedup vs baseline: 2.7264x; 1.1632x over previous
#include <cuda_runtime.h>
#include <cuda_bf16.h>
#include <math.h>

#define CN (256*1024)

// ---------------- device scratch ----------------
__device__ float g_x[2*256*1024];     // LN1 out, (B,C,N)
__device__ float g_q[2*256*1024];     // q proj (B,C,N), unscaled
__device__ float g_vgrid[16*64*2];    // normalized kv coords per (b,g)
__device__ float g_k[2*256*64];
__device__ float g_v[2*256*64];
__device__ float g_attn[2*1024*256];  // attention out (b,n,c)
__device__ float g_srcp[2*1024*256];  // src + out proj (b,n,c)
__device__ float g_src2[2*1024*256];  // LN2 out
__device__ float g_ffnh[2*1024*1024]; // ffn hidden

__device__ __forceinline__ unsigned pack_bf16(float lo, float hi) {
    __nv_bfloat162 v = __floats2bfloat162_rn(lo, hi);
    return *(unsigned*)&v;
}

__device__ __forceinline__ void mma_bf16(float& c0, float& c1, float& c2, float& c3,
        unsigned a0, unsigned a1, unsigned a2, unsigned a3,
        unsigned b0, unsigned b1) {
    asm volatile("mma.sync.aligned.m16n8k16.row.col.f32.bf16.bf16.f32 "
        "{%0,%1,%2,%3}, {%4,%5,%6,%7}, {%8,%9}, {%0,%1,%2,%3};"
        : "+f"(c0), "+f"(c1), "+f"(c2), "+f"(c3)
        : "r"(a0), "r"(a1), "r"(a2), "r"(a3), "r"(b0), "r"(b1));
}

__device__ __forceinline__ void mma_tf32(float& c0, float& c1, float& c2, float& c3,
        unsigned a0, unsigned a1, unsigned a2, unsigned a3,
        unsigned b0, unsigned b1) {
    asm volatile("mma.sync.aligned.m16n8k8.row.col.f32.tf32.tf32.f32 "
        "{%0,%1,%2,%3}, {%4,%5,%6,%7}, {%8,%9}, {%0,%1,%2,%3};"
        : "+f"(c0), "+f"(c1), "+f"(c2), "+f"(c3)
        : "r"(a0), "r"(a1), "r"(a2), "r"(a3), "r"(b0), "r"(b1));
}

__device__ __forceinline__ unsigned f2tf32(float f) {
    unsigned u;
    asm("cvt.rna.tf32.f32 %0, %1;" : "=r"(u) : "f"(f));
    return u;
}

// ---------------- LayerNorm ----------------
__global__ void ln_kernel(const float* __restrict__ in, const float* __restrict__ gma,
                          const float* __restrict__ bta, float* __restrict__ out, int to_chw) {
    int row = blockIdx.x;
    int t = threadIdx.x;
    float v = in[row*256 + t];
    float s = v, sq = v*v;
    #pragma unroll
    for (int o = 16; o; o >>= 1) {
        s  += __shfl_down_sync(0xffffffffu, s,  o);
        sq += __shfl_down_sync(0xffffffffu, sq, o);
    }
    __shared__ float ps[8], pq[8], mb[2];
    int w = t >> 5, l = t & 31;
    if (!l) { ps[w] = s; pq[w] = sq; }
    __syncthreads();
    if (!t) {
        float S = 0.f, Q = 0.f;
        #pragma unroll
        for (int i = 0; i < 8; i++) { S += ps[i]; Q += pq[i]; }
        float m = S * (1.f/256.f);
        float var = Q * (1.f/256.f) - m*m;
        mb[0] = m; mb[1] = rsqrtf(var + 1e-5f);
    }
    __syncthreads();
    float y = (v - mb[0]) * mb[1] * gma[t] + bta[t];
    if (to_chw) { int b = row >> 10, n = row & 1023; out[b*CN + t*1024 + n] = y; }
    else        out[row*256 + t] = y;
}

// ---------------- grouped 1x1 q projection ----------------
__global__ void qproj_kernel(const float* __restrict__ wq) {
    int bg = blockIdx.x; int b = bg >> 3, g = bg & 7;
    int n0 = blockIdx.y * 128;
    int t = threadIdx.x;
    __shared__ float wqs[1024], xs[32*128];
    for (int i = t; i < 1024; i += 256) wqs[i] = wq[g*1024 + i];
    for (int i = t; i < 4096; i += 256) {
        int c = i >> 7, nn = i & 127;
        xs[c*128 + nn] = g_x[b*CN + (g*32 + c)*1024 + n0 + nn];
    }
    __syncthreads();
    for (int i = t; i < 4096; i += 256) {
        int o = i >> 7, nn = i & 127;
        float a = 0.f;
        #pragma unroll
        for (int c = 0; c < 32; c++) a += xs[c*128 + nn] * wqs[o*32 + c];
        g_q[b*CN + (g*32 + o)*1024 + n0 + nn] = a;
    }
}

// --- fused: depthwise conv + GELU + offset proj + tanh + grid_sample + k/v proj ---
__global__ void offset_sample_kv_kernel(const float* __restrict__ wdw, const float* __restrict__ bdw,
                                        const float* __restrict__ woff,
                                        const float* __restrict__ wk, const float* __restrict__ wv) {
    int bg = blockIdx.x; int b = bg >> 3, g = bg & 7;
    int t = threadIdx.x;
    __shared__ float wdws[1152], bdws[32], woffs[64], sg[2048], coords[128];
    __shared__ float samp[2048], wks[1024], wvs[1024];
    for (int i = t; i < 1152; i += 256) wdws[i] = wdw[i];
    if (t < 32) bdws[t] = bdw[t];
    if (t < 64) woffs[t] = woff[t];
    for (int i = t; i < 1024; i += 256) { wks[i] = wk[g*1024 + i]; wvs[i] = wv[g*1024 + i]; }
    __syncthreads();

    const float* qg = g_q + b*CN + g*32*1024;
    for (int i = t; i < 2048; i += 256) {
        int c = i >> 6, pos = i & 63, oy = pos >> 3, ox = pos & 7;
        float a = 0.f;
        #pragma unroll
        for (int ky = 0; ky < 6; ky++) {
            int iy = oy*4 - 1 + ky;
            if ((unsigned)iy < 32u) {
                #pragma unroll
                for (int kx = 0; kx < 6; kx++) {
                    int ix = ox*4 - 1 + kx;
                    if ((unsigned)ix < 32u)
                        a += qg[c*1024 + iy*32 + ix] * wdws[c*36 + ky*6 + kx];
                }
            }
        }
        a += bdws[c];
        sg[c*64 + pos] = 0.5f * a * (1.f + erff(a * 0.70710678118654752f));
    }
    __syncthreads();
    if (t < 128) {
        int pos = t >> 1, comp = t & 1;
        float s = 0.f;
        #pragma unroll
        for (int c = 0; c < 32; c++) s += sg[c*64 + pos] * woffs[comp*32 + c];
        float off = tanhf(s) * 4.f;
        float base = comp ? (float)(pos >> 3) : (float)(pos & 7);
        float gn = 2.f * (base + off) * (1.f/7.f) - 1.f;
        coords[pos*2 + comp] = gn;
        g_vgrid[bg*128 + pos*2 + comp] = gn;
    }
    __syncthreads();
    const float* xg = g_x + b*CN + g*32*1024;
    for (int i = t; i < 2048; i += 256) {
        int c = i >> 6, pos = i & 63;
        float xf = ((coords[pos*2 + 0] + 1.f)*32.f - 1.f)*0.5f;
        float yf = ((coords[pos*2 + 1] + 1.f)*32.f - 1.f)*0.5f;
        float x0f = floorf(xf), y0f = floorf(yf);
        int x0 = (int)x0f, y0 = (int)y0f;
        float wx1 = xf - x0f, wx0 = 1.f - wx1, wy1 = yf - y0f, wy0 = 1.f - wy1;
        float acc = 0.f;
        #pragma unroll
        for (int dy = 0; dy < 2; dy++) {
            int iy = y0 + dy;
            if ((unsigned)iy >= 32u) continue;
            float wy = dy ? wy1 : wy0;
            #pragma unroll
            for (int dx = 0; dx < 2; dx++) {
                int ix = x0 + dx;
                if ((unsigned)ix >= 32u) continue;
                float wxx = dx ? wx1 : wx0;
                acc += xg[c*1024 + iy*32 + ix] * wxx * wy;
            }
        }
        samp[c*64 + pos] = acc;
    }
    __syncthreads();
    for (int i = t; i < 2048; i += 256) {
        int o = i >> 6, j = i & 63;
        float ak = 0.f, av = 0.f;
        #pragma unroll
        for (int c = 0; c < 32; c++) {
            float f = samp[c*64 + j];
            ak += f * wks[o*32 + c];
            av += f * wvs[o*32 + c];
        }
        g_k[(b*256 + g*32 + o)*64 + j] = ak;
        g_v[(b*256 + g*32 + o)*64 + j] = av;
    }
}

// -------- fused attention: sim + CPB MLP (both layers on tensor cores) + softmax + attn@v --------
__global__ __launch_bounds__(256) void attn_kernel(
        const float* __restrict__ w0, const float* __restrict__ b0p,
        const float* __restrict__ w1, const float* __restrict__ b1p,
        const float* __restrict__ w2, const float* __restrict__ b2p) {
    int bh = blockIdx.y; int b = bh >> 3, h = bh & 7;
    int i0 = blockIdx.x * 32;
    int t = threadIdx.x, w = t >> 5, l = t & 31, g = l >> 2, tig = l & 3;

    __shared__ __align__(16) float ks[64*36];
    __shared__ __align__(16) float vs[64*36];
    __shared__ __align__(16) float qs[32*36];
    __shared__ __align__(16) unsigned W1v[32*68];   // per-lane packed B fragments of W1
    __shared__ __align__(16) unsigned pf[2048];     // pack_bf16(fx, fy) per pair
    __shared__ __align__(16) float b1s[64];
    __shared__ __align__(16) float w2s[64];
    __shared__ float logits[2048];

    if (t < 64) { b1s[t] = b1p[t]; w2s[t] = w2[t]; }
    for (int i = t; i < 2048; i += 256) {
        int d = i >> 6, j = i & 63;
        ks[j*36 + d] = g_k[(b*256 + h*32 + d)*64 + j];
        vs[j*36 + d] = g_v[(b*256 + h*32 + d)*64 + j];
    }
    for (int i = t; i < 1024; i += 256) {
        int d = i >> 5, ii = i & 31;
        qs[ii*36 + d] = g_q[b*CN + (h*32 + d)*1024 + i0 + ii] * 0.17677669529663687f;
    }
    // pack W1 -> per-lane bf16x2 B fragments, vector-load friendly:
    // W1v[l*68 + nt*8 + kt*2 + reg]
    for (int i = t; i < 2048; i += 256) {
        int ll = i >> 6, rem = i & 63;
        int nt = rem >> 3, q = rem & 7;
        int kt = q >> 1, reg = q & 1;
        int gg = ll >> 2, ti = ll & 3;
        int k = kt*16 + reg*8 + ti*2;
        int col = nt*8 + gg;
        W1v[ll*68 + nt*8 + q] = pack_bf16(w1[k*64 + col], w1[(k+1)*64 + col]);
    }
    // packed CPB features per pair
    float py = 2.f * (float)blockIdx.x * (1.f/31.f) - 1.f;
    for (int i = t; i < 2048; i += 256) {
        int ii = i >> 6, j = i & 63;
        float px = 2.f * (float)ii * (1.f/31.f) - 1.f;
        float dx = px - g_vgrid[bh*128 + 2*j];
        float dy = py - g_vgrid[bh*128 + 2*j + 1];
        float fx = copysignf(log1pf(fabsf(dx)), dx);
        float fy = copysignf(log1pf(fabsf(dy)), dy);
        pf[i] = pack_bf16(fx, fy);
    }

    // hoist layer-0 B fragments: E rows: 0=W0x, 1=W0y, 2=b0, rest 0
    unsigned w0b[8];
    #pragma unroll
    for (int nt = 0; nt < 8; nt++) {
        int col = nt*8 + g;
        w0b[nt] = (tig == 0) ? pack_bf16(w0[col], w0[64 + col])
                : (tig == 1) ? pack_bf16(b0p[col], 0.f) : 0u;
    }
    __syncthreads();

    float b2v = b2p[0];
    const uint4* W1v4 = (const uint4*)W1v;
    const float4* qs4 = (const float4*)qs;
    const float4* ks4 = (const float4*)ks;
    const float4* vs4 = (const float4*)vs;
    const unsigned ONE_PACK = 0x00003F80u;   // pack_bf16(1.0f, 0.0f)

    int pbase = w*256;
    for (int mt = 0; mt < 16; mt++) {
        int p0 = pbase + mt*16 + g;
        int p1 = p0 + 8;
        // layer-0 A fragments: rows = (fx, fy, 1, 0, ...) in K=16
        unsigned pf0 = pf[p0], pf1 = pf[p1];
        unsigned af0 = (tig == 0) ? pf0 : (tig == 1) ? ONE_PACK : 0u;
        unsigned af1 = (tig == 0) ? pf1 : (tig == 1) ? ONE_PACK : 0u;

        // layer-0: h1 = relu(W0^T f + b0) — fragments land exactly where layer-1 A needs them
        float hc[8][4];
        #pragma unroll
        for (int nt = 0; nt < 8; nt++) {
            hc[nt][0] = hc[nt][1] = hc[nt][2] = hc[nt][3] = 0.f;
            mma_bf16(hc[nt][0], hc[nt][1], hc[nt][2], hc[nt][3],
                     af0, af1, 0u, 0u, w0b[nt], 0u);
        }
        unsigned a[4][4];
        #pragma unroll
        for (int kt = 0; kt < 4; kt++) {
            a[kt][0] = pack_bf16(fmaxf(hc[2*kt][0], 0.f),   fmaxf(hc[2*kt][1], 0.f));
            a[kt][1] = pack_bf16(fmaxf(hc[2*kt][2], 0.f),   fmaxf(hc[2*kt][3], 0.f));
            a[kt][2] = pack_bf16(fmaxf(hc[2*kt+1][0], 0.f), fmaxf(hc[2*kt+1][1], 0.f));
            a[kt][3] = pack_bf16(fmaxf(hc[2*kt+1][2], 0.f), fmaxf(hc[2*kt+1][3], 0.f));
        }

        // layer-1 + epilogue
        float acc0 = 0.f, acc1 = 0.f;
        #pragma unroll
        for (int nt = 0; nt < 8; nt++) {
            uint4 u0 = W1v4[l*17 + nt*2];
            uint4 u1 = W1v4[l*17 + nt*2 + 1];
            float c0 = 0.f, c1 = 0.f, c2 = 0.f, c3 = 0.f;
            mma_bf16(c0, c1, c2, c3, a[0][0], a[0][1], a[0][2], a[0][3], u0.x, u0.y);
            mma_bf16(c0, c1, c2, c3, a[1][0], a[1][1], a[1][2], a[1][3], u0.z, u0.w);
            mma_bf16(c0, c1, c2, c3, a[2][0], a[2][1], a[2][2], a[2][3], u1.x, u1.y);
            mma_bf16(c0, c1, c2, c3, a[3][0], a[3][1], a[3][2], a[3][3], u1.z, u1.w);
            int col0 = nt*8 + 2*tig;
            float2 b1v = *(const float2*)&b1s[col0];
            float2 w2v = *(const float2*)&w2s[col0];
            acc0 += fmaxf(c0 + b1v.x, 0.f)*w2v.x + fmaxf(c1 + b1v.y, 0.f)*w2v.y;
            acc1 += fmaxf(c2 + b1v.x, 0.f)*w2v.x + fmaxf(c3 + b1v.y, 0.f)*w2v.y;
        }

        // q.k partial sums (each quad-lane covers 8 dims)
        int ii0 = p0 >> 6, j0 = p0 & 63;
        int ii1 = p1 >> 6, j1 = p1 & 63;
        float4 qa = qs4[ii0*9 + tig*2], qb = qs4[ii0*9 + tig*2 + 1];
        float4 ka = ks4[j0*9 + tig*2], kb = ks4[j0*9 + tig*2 + 1];
        acc0 += qa.x*ka.x + qa.y*ka.y + qa.z*ka.z + qa.w*ka.w
              + qb.x*kb.x + qb.y*kb.y + qb.z*kb.z + qb.w*kb.w;
        float4 qc = qs4[ii1*9 + tig*2], qd = qs4[ii1*9 + tig*2 + 1];
        float4 kc = ks4[j1*9 + tig*2], kd = ks4[j1*9 + tig*2 + 1];
        acc1 += qc.x*kc.x + qc.y*kc.y + qc.z*kc.z + qc.w*kc.w
              + qd.x*kd.x + qd.y*kd.y + qd.z*kd.z + qd.w*kd.w;

        acc0 += __shfl_xor_sync(0xffffffffu, acc0, 1);
        acc0 += __shfl_xor_sync(0xffffffffu, acc0, 2);
        acc1 += __shfl_xor_sync(0xffffffffu, acc1, 1);
        acc1 += __shfl_xor_sync(0xffffffffu, acc1, 2);
        if (tig == 0) { logits[p0] = acc0 + b2v; logits[p1] = acc1 + b2v; }
    }
    __syncthreads();

    // softmax over j=64 per row
    for (int rr = 0; rr < 4; rr++) {
        int row = w*4 + rr;
        float l0 = logits[row*64 + l], l1 = logits[row*64 + 32 + l];
        float m = fmaxf(l0, l1);
        #pragma unroll
        for (int o = 16; o; o >>= 1) m = fmaxf(m, __shfl_xor_sync(0xffffffffu, m, o));
        float e0 = __expf(l0 - m), e1 = __expf(l1 - m);
        float ss = e0 + e1;
        #pragma unroll
        for (int o = 16; o; o >>= 1) ss += __shfl_xor_sync(0xffffffffu, ss, o);
        float inv = 1.f / ss;
        logits[row*64 + l] = e0*inv;
        logits[row*64 + 32 + l] = e1*inv;
    }
    __syncthreads();

    // attn @ v, vectorized over d
    {
        int ii = t >> 3, dq = (t & 7);
        float4 acc = make_float4(0.f, 0.f, 0.f, 0.f);
        #pragma unroll 8
        for (int j = 0; j < 64; j++) {
            float lw = logits[ii*64 + j];
            float4 vv = vs4[j*9 + dq];
            acc.x += lw*vv.x; acc.y += lw*vv.y; acc.z += lw*vv.z; acc.w += lw*vv.w;
        }
        *(float4*)&g_attn[(b*1024 + i0 + ii)*256 + h*32 + dq*4] = acc;
    }
}

// ---------------- tf32 tensor-core GEMM with fused epilogue ----------------
// A: MxK row-major. BT=false: B is KxN. BT=true: B is NxK (C = A @ B^T).
// EPI 0: C = acc + bias[col] + res[row,col] ; EPI 1: C = relu(acc + bias[col])
template<bool BT, int EPI>
__global__ __launch_bounds__(256) void gemm_tf32(
        const float* __restrict__ A, const float* __restrict__ B,
        const float* __restrict__ bias, const float* __restrict__ res,
        float* __restrict__ C, int M, int N, int K) {
    const int m0 = blockIdx.y * 64, n0 = blockIdx.x * 64;
    __shared__ __align__(16) unsigned As[64*20];
    __shared__ __align__(16) unsigned Bs[64*20];   // stored n-major: Bs[n][k]
    int t = threadIdx.x, w = t >> 5, l = t & 31, g = l >> 2, ti = l & 3;
    int mw = (w & 3) * 16, nw = (w >> 2) * 32;

    float c[4][4];
    #pragma unroll
    for (int i = 0; i < 4; i++)
        #pragma unroll
        for (int j = 0; j < 4; j++) c[i][j] = 0.f;

    for (int k0 = 0; k0 < K; k0 += 16) {
        {
            int r = t >> 2, c4 = (t & 3) * 4;
            float4 v = *(const float4*)&A[(m0 + r)*K + k0 + c4];
            uint4 u = make_uint4(f2tf32(v.x), f2tf32(v.y), f2tf32(v.z), f2tf32(v.w));
            *(uint4*)&As[r*20 + c4] = u;
        }
        if (BT) {
            int r = t >> 2, c4 = (t & 3) * 4;
            float4 v = *(const float4*)&B[(n0 + r)*K + k0 + c4];
            uint4 u = make_uint4(f2tf32(v.x), f2tf32(v.y), f2tf32(v.z), f2tf32(v.w));
            *(uint4*)&Bs[r*20 + c4] = u;
        } else {
            int r = t >> 4, c4 = (t & 15) * 4;
            float4 v = *(const float4*)&B[(k0 + r)*N + n0 + c4];
            Bs[(c4+0)*20 + r] = f2tf32(v.x);
            Bs[(c4+1)*20 + r] = f2tf32(v.y);
            Bs[(c4+2)*20 + r] = f2tf32(v.z);
            Bs[(c4+3)*20 + r] = f2tf32(v.w);
        }
        __syncthreads();
        #pragma unroll
        for (int kk = 0; kk < 16; kk += 8) {
            unsigned a0 = As[(mw + g)*20 + kk + ti];
            unsigned a1 = As[(mw + g + 8)*20 + kk + ti];
            unsigned a2 = As[(mw + g)*20 + kk + ti + 4];
            unsigned a3 = As[(mw + g + 8)*20 + kk + ti + 4];
            #pragma unroll
            for (int nt = 0; nt < 4; nt++) {
                int nc = nw + nt*8 + g;
                unsigned b0 = Bs[nc*20 + kk + ti];
                unsigned b1 = Bs[nc*20 + kk + ti + 4];
                mma_tf32(c[nt][0], c[nt][1], c[nt][2], c[nt][3], a0, a1, a2, a3, b0, b1);
            }
        }
        __syncthreads();
    }
    #pragma unroll
    for (int nt = 0; nt < 4; nt++) {
        int col = n0 + nw + nt*8 + 2*ti;
        int r0 = m0 + mw + g, r1 = r0 + 8;
        float2 bi = *(const float2*)&bias[col];
        float2 v0 = make_float2(c[nt][0] + bi.x, c[nt][1] + bi.y);
        float2 v1 = make_float2(c[nt][2] + bi.x, c[nt][3] + bi.y);
        if (EPI == 1) {
            v0.x = fmaxf(v0.x, 0.f); v0.y = fmaxf(v0.y, 0.f);
            v1.x = fmaxf(v1.x, 0.f); v1.y = fmaxf(v1.y, 0.f);
        } else {
            float2 r0v = *(const float2*)&res[r0*N + col];
            float2 r1v = *(const float2*)&res[r1*N + col];
            v0.x += r0v.x; v0.y += r0v.y;
            v1.x += r1v.x; v1.y += r1v.y;
        }
        *(float2*)&C[r0*N + col] = v0;
        *(float2*)&C[r1*N + col] = v1;
    }
}

// ---------------- launcher ----------------
extern "C" void kernel_launch(void* const* d_in, const int* in_sizes, int n_in,
                              void* d_out, int out_size) {
    const float* src     = (const float*)d_in[0];
    const float* norm1_g = (const float*)d_in[1];
    const float* norm1_b = (const float*)d_in[2];
    const float* wq      = (const float*)d_in[3];
    const float* wdw     = (const float*)d_in[4];
    const float* bdw     = (const float*)d_in[5];
    const float* woff    = (const float*)d_in[6];
    const float* wk      = (const float*)d_in[7];
    const float* wv      = (const float*)d_in[8];
    const float* cpb_w0  = (const float*)d_in[9];
    const float* cpb_b0  = (const float*)d_in[10];
    const float* cpb_w1  = (const float*)d_in[11];
    const float* cpb_b1  = (const float*)d_in[12];
    const float* cpb_w2  = (const float*)d_in[13];
    const float* cpb_b2  = (const float*)d_in[14];
    const float* wout    = (const float*)d_in[15];
    const float* bout    = (const float*)d_in[16];
    const float* norm2_g = (const float*)d_in[17];
    const float* norm2_b = (const float*)d_in[18];
    const float* ffn_w1  = (const float*)d_in[19];
    const float* ffn_b1  = (const float*)d_in[20];
    const float* ffn_w2  = (const float*)d_in[21];
    const float* ffn_b2  = (const float*)d_in[22];

    void *p_x, *p_attn, *p_srcp, *p_src2, *p_ffnh;
    cudaGetSymbolAddress(&p_x,    g_x);
    cudaGetSymbolAddress(&p_attn, g_attn);
    cudaGetSymbolAddress(&p_srcp, g_srcp);
    cudaGetSymbolAddress(&p_src2, g_src2);
    cudaGetSymbolAddress(&p_ffnh, g_ffnh);

    ln_kernel<<<2048, 256>>>(src, norm1_g, norm1_b, (float*)p_x, 1);
    qproj_kernel<<<dim3(16, 8), 256>>>(wq);
    offset_sample_kv_kernel<<<16, 256>>>(wdw, bdw, woff, wk, wv);
    attn_kernel<<<dim3(32, 16), 256>>>(cpb_w0, cpb_b0, cpb_w1, cpb_b1, cpb_w2, cpb_b2);
    gemm_tf32<true, 0><<<dim3(4, 32), 256>>>((const float*)p_attn, wout, bout, src,
                                             (float*)p_srcp, 2048, 256, 256);
    ln_kernel<<<2048, 256>>>((const float*)p_srcp, norm2_g, norm2_b, (float*)p_src2, 0);
    gemm_tf32<false, 1><<<dim3(16, 32), 256>>>((const float*)p_src2, ffn_w1, ffn_b1, nullptr,
                                               (float*)p_ffnh, 2048, 1024, 256);
    gemm_tf32<false, 0><<<dim3(4, 32), 256>>>((const float*)p_ffnh, ffn_w2, ffn_b2,
                                              (const float*)p_srcp, (float*)d_out,
                                              2048, 256, 1024);
}

// round 4
// speedup vs baseline: 2.9166x; 1.0698x over previous
#include <cuda_runtime.h>
#include <cuda_bf16.h>
#include <math.h>

#define CN (256*1024)

// ---------------- device scratch ----------------
__device__ float g_x[2*256*1024];     // LN1 out, (B,C,N)
__device__ float g_q[2*256*1024];     // q proj (B,C,N), unscaled
__device__ float g_vgrid[16*64*2];    // normalized kv coords per (b,g)
__device__ float g_k[2*256*64];
__device__ float g_v[2*256*64];
__device__ float g_attn[2*1024*256];  // attention out (b,n,c)
__device__ float g_srcp[2*1024*256];  // src + out proj (b,n,c)
__device__ float g_src2[2*1024*256];  // LN2 out
__device__ float g_ffnh[2*1024*1024]; // ffn hidden

__device__ __forceinline__ unsigned pack_bf16(float lo, float hi) {
    __nv_bfloat162 v = __floats2bfloat162_rn(lo, hi);
    return *(unsigned*)&v;
}

__device__ __forceinline__ void mma_bf16(float& c0, float& c1, float& c2, float& c3,
        unsigned a0, unsigned a1, unsigned a2, unsigned a3,
        unsigned b0, unsigned b1) {
    asm volatile("mma.sync.aligned.m16n8k16.row.col.f32.bf16.bf16.f32 "
        "{%0,%1,%2,%3}, {%4,%5,%6,%7}, {%8,%9}, {%0,%1,%2,%3};"
        : "+f"(c0), "+f"(c1), "+f"(c2), "+f"(c3)
        : "r"(a0), "r"(a1), "r"(a2), "r"(a3), "r"(b0), "r"(b1));
}

__device__ __forceinline__ void mma_tf32(float& c0, float& c1, float& c2, float& c3,
        unsigned a0, unsigned a1, unsigned a2, unsigned a3,
        unsigned b0, unsigned b1) {
    asm volatile("mma.sync.aligned.m16n8k8.row.col.f32.tf32.tf32.f32 "
        "{%0,%1,%2,%3}, {%4,%5,%6,%7}, {%8,%9}, {%0,%1,%2,%3};"
        : "+f"(c0), "+f"(c1), "+f"(c2), "+f"(c3)
        : "r"(a0), "r"(a1), "r"(a2), "r"(a3), "r"(b0), "r"(b1));
}

__device__ __forceinline__ unsigned f2tf32(float f) {
    unsigned u;
    asm("cvt.rna.tf32.f32 %0, %1;" : "=r"(u) : "f"(f));
    return u;
}

// ---------------- LayerNorm ----------------
__global__ void ln_kernel(const float* __restrict__ in, const float* __restrict__ gma,
                          const float* __restrict__ bta, float* __restrict__ out, int to_chw) {
    int row = blockIdx.x;
    int t = threadIdx.x;
    float v = in[row*256 + t];
    float s = v, sq = v*v;
    #pragma unroll
    for (int o = 16; o; o >>= 1) {
        s  += __shfl_down_sync(0xffffffffu, s,  o);
        sq += __shfl_down_sync(0xffffffffu, sq, o);
    }
    __shared__ float ps[8], pq[8], mb[2];
    int w = t >> 5, l = t & 31;
    if (!l) { ps[w] = s; pq[w] = sq; }
    __syncthreads();
    if (!t) {
        float S = 0.f, Q = 0.f;
        #pragma unroll
        for (int i = 0; i < 8; i++) { S += ps[i]; Q += pq[i]; }
        float m = S * (1.f/256.f);
        float var = Q * (1.f/256.f) - m*m;
        mb[0] = m; mb[1] = rsqrtf(var + 1e-5f);
    }
    __syncthreads();
    float y = (v - mb[0]) * mb[1] * gma[t] + bta[t];
    if (to_chw) { int b = row >> 10, n = row & 1023; out[b*CN + t*1024 + n] = y; }
    else        out[row*256 + t] = y;
}

// ---------------- grouped 1x1 q projection ----------------
__global__ void qproj_kernel(const float* __restrict__ wq) {
    int bg = blockIdx.x; int b = bg >> 3, g = bg & 7;
    int n0 = blockIdx.y * 128;
    int t = threadIdx.x;
    __shared__ float wqs[1024], xs[32*128];
    for (int i = t; i < 1024; i += 256) wqs[i] = wq[g*1024 + i];
    for (int i = t; i < 4096; i += 256) {
        int c = i >> 7, nn = i & 127;
        xs[c*128 + nn] = g_x[b*CN + (g*32 + c)*1024 + n0 + nn];
    }
    __syncthreads();
    for (int i = t; i < 4096; i += 256) {
        int o = i >> 7, nn = i & 127;
        float a = 0.f;
        #pragma unroll
        for (int c = 0; c < 32; c++) a += xs[c*128 + nn] * wqs[o*32 + c];
        g_q[b*CN + (g*32 + o)*1024 + n0 + nn] = a;
    }
}

// --- fused: depthwise conv + GELU + offset proj + tanh + grid_sample + k/v proj ---
__global__ void offset_sample_kv_kernel(const float* __restrict__ wdw, const float* __restrict__ bdw,
                                        const float* __restrict__ woff,
                                        const float* __restrict__ wk, const float* __restrict__ wv) {
    int bg = blockIdx.x; int b = bg >> 3, g = bg & 7;
    int t = threadIdx.x;
    __shared__ float wdws[1152], bdws[32], woffs[64], sg[2048], coords[128];
    __shared__ float samp[2048], wks[1024], wvs[1024];
    for (int i = t; i < 1152; i += 256) wdws[i] = wdw[i];
    if (t < 32) bdws[t] = bdw[t];
    if (t < 64) woffs[t] = woff[t];
    for (int i = t; i < 1024; i += 256) { wks[i] = wk[g*1024 + i]; wvs[i] = wv[g*1024 + i]; }
    __syncthreads();

    const float* qg = g_q + b*CN + g*32*1024;
    for (int i = t; i < 2048; i += 256) {
        int c = i >> 6, pos = i & 63, oy = pos >> 3, ox = pos & 7;
        float a = 0.f;
        #pragma unroll
        for (int ky = 0; ky < 6; ky++) {
            int iy = oy*4 - 1 + ky;
            if ((unsigned)iy < 32u) {
                #pragma unroll
                for (int kx = 0; kx < 6; kx++) {
                    int ix = ox*4 - 1 + kx;
                    if ((unsigned)ix < 32u)
                        a += qg[c*1024 + iy*32 + ix] * wdws[c*36 + ky*6 + kx];
                }
            }
        }
        a += bdws[c];
        sg[c*64 + pos] = 0.5f * a * (1.f + erff(a * 0.70710678118654752f));
    }
    __syncthreads();
    if (t < 128) {
        int pos = t >> 1, comp = t & 1;
        float s = 0.f;
        #pragma unroll
        for (int c = 0; c < 32; c++) s += sg[c*64 + pos] * woffs[comp*32 + c];
        float off = tanhf(s) * 4.f;
        float base = comp ? (float)(pos >> 3) : (float)(pos & 7);
        float gn = 2.f * (base + off) * (1.f/7.f) - 1.f;
        coords[pos*2 + comp] = gn;
        g_vgrid[bg*128 + pos*2 + comp] = gn;
    }
    __syncthreads();
    const float* xg = g_x + b*CN + g*32*1024;
    for (int i = t; i < 2048; i += 256) {
        int c = i >> 6, pos = i & 63;
        float xf = ((coords[pos*2 + 0] + 1.f)*32.f - 1.f)*0.5f;
        float yf = ((coords[pos*2 + 1] + 1.f)*32.f - 1.f)*0.5f;
        float x0f = floorf(xf), y0f = floorf(yf);
        int x0 = (int)x0f, y0 = (int)y0f;
        float wx1 = xf - x0f, wx0 = 1.f - wx1, wy1 = yf - y0f, wy0 = 1.f - wy1;
        float acc = 0.f;
        #pragma unroll
        for (int dy = 0; dy < 2; dy++) {
            int iy = y0 + dy;
            if ((unsigned)iy >= 32u) continue;
            float wy = dy ? wy1 : wy0;
            #pragma unroll
            for (int dx = 0; dx < 2; dx++) {
                int ix = x0 + dx;
                if ((unsigned)ix >= 32u) continue;
                float wxx = dx ? wx1 : wx0;
                acc += xg[c*1024 + iy*32 + ix] * wxx * wy;
            }
        }
        samp[c*64 + pos] = acc;
    }
    __syncthreads();
    for (int i = t; i < 2048; i += 256) {
        int o = i >> 6, j = i & 63;
        float ak = 0.f, av = 0.f;
        #pragma unroll
        for (int c = 0; c < 32; c++) {
            float f = samp[c*64 + j];
            ak += f * wks[o*32 + c];
            av += f * wvs[o*32 + c];
        }
        g_k[(b*256 + g*32 + o)*64 + j] = ak;
        g_v[(b*256 + g*32 + o)*64 + j] = av;
    }
}

// -------- fused attention: everything on tensor cores --------
__global__ __launch_bounds__(256, 3) void attn_kernel(
        const float* __restrict__ w0, const float* __restrict__ b0p,
        const float* __restrict__ w1, const float* __restrict__ b1p,
        const float* __restrict__ w2, const float* __restrict__ b2p) {
    int bh = blockIdx.y; int b = bh >> 3, h = bh & 7;
    int i0 = blockIdx.x * 32;
    int t = threadIdx.x, w = t >> 5, l = t & 31, g = l >> 2, tig = l & 3;

    __shared__ __align__(16) float ks[64*36];
    __shared__ __align__(16) float vs[64*36];
    __shared__ __align__(16) float qs[32*36];
    __shared__ __align__(16) unsigned W1v[32*68];   // per-lane packed B fragments of W1
    __shared__ __align__(16) unsigned pf[2048];     // pack_bf16(fx, fy) per pair
    __shared__ __align__(16) float b1s[64];
    __shared__ __align__(16) float w2s[64];
    __shared__ __align__(16) float logits[32*68];   // stride 68: conflict-free frags

    if (t < 64) { b1s[t] = b1p[t]; w2s[t] = w2[t]; }
    for (int i = t; i < 2048; i += 256) {
        int d = i >> 6, j = i & 63;
        ks[j*36 + d] = g_k[(b*256 + h*32 + d)*64 + j];
        vs[j*36 + d] = g_v[(b*256 + h*32 + d)*64 + j];
    }
    for (int i = t; i < 1024; i += 256) {
        int d = i >> 5, ii = i & 31;
        qs[ii*36 + d] = g_q[b*CN + (h*32 + d)*1024 + i0 + ii] * 0.17677669529663687f;
    }
    // pack W1 -> per-lane bf16x2 B fragments: W1v[l*68 + nt*8 + kt*2 + reg]
    for (int i = t; i < 2048; i += 256) {
        int ll = i >> 6, rem = i & 63;
        int nt = rem >> 3, q = rem & 7;
        int kt = q >> 1, reg = q & 1;
        int gg = ll >> 2, ti = ll & 3;
        int k = kt*16 + reg*8 + ti*2;
        int col = nt*8 + gg;
        W1v[ll*68 + nt*8 + q] = pack_bf16(w1[k*64 + col], w1[(k+1)*64 + col]);
    }
    // packed CPB features per pair (fast log: bf16 packing swamps the approx error)
    float py = 2.f * (float)blockIdx.x * (1.f/31.f) - 1.f;
    for (int i = t; i < 2048; i += 256) {
        int ii = i >> 6, j = i & 63;
        float px = 2.f * (float)ii * (1.f/31.f) - 1.f;
        float dx = px - g_vgrid[bh*128 + 2*j];
        float dy = py - g_vgrid[bh*128 + 2*j + 1];
        float fx = copysignf(__logf(1.f + fabsf(dx)), dx);
        float fy = copysignf(__logf(1.f + fabsf(dy)), dy);
        pf[i] = pack_bf16(fx, fy);
    }
    // hoist layer-0 B fragments
    unsigned w0b[8];
    #pragma unroll
    for (int nt = 0; nt < 8; nt++) {
        int col = nt*8 + g;
        w0b[nt] = (tig == 0) ? pack_bf16(w0[col], w0[64 + col])
                : (tig == 1) ? pack_bf16(b0p[col], 0.f) : 0u;
    }
    __syncthreads();

    float b2v = b2p[0];

    // ---- sim = Q K^T via tf32 mma; warp w: rows (w&1)*16.., cols (w>>1)*16.. ----
    {
        int m0w = (w & 1) * 16, n0w = (w >> 1) * 16;
        float c[2][4];
        #pragma unroll
        for (int nt = 0; nt < 2; nt++)
            c[nt][0] = c[nt][1] = c[nt][2] = c[nt][3] = 0.f;
        #pragma unroll
        for (int kk = 0; kk < 32; kk += 8) {
            unsigned a0 = f2tf32(qs[(m0w + g)*36 + kk + tig]);
            unsigned a1 = f2tf32(qs[(m0w + g + 8)*36 + kk + tig]);
            unsigned a2 = f2tf32(qs[(m0w + g)*36 + kk + tig + 4]);
            unsigned a3 = f2tf32(qs[(m0w + g + 8)*36 + kk + tig + 4]);
            #pragma unroll
            for (int nt = 0; nt < 2; nt++) {
                int j = n0w + nt*8 + g;
                unsigned b0 = f2tf32(ks[j*36 + kk + tig]);
                unsigned b1 = f2tf32(ks[j*36 + kk + tig + 4]);
                mma_tf32(c[nt][0], c[nt][1], c[nt][2], c[nt][3], a0, a1, a2, a3, b0, b1);
            }
        }
        #pragma unroll
        for (int nt = 0; nt < 2; nt++) {
            int col = n0w + nt*8 + 2*tig;
            *(float2*)&logits[(m0w + g)*68 + col]     = make_float2(c[nt][0] + b2v, c[nt][1] + b2v);
            *(float2*)&logits[(m0w + g + 8)*68 + col] = make_float2(c[nt][2] + b2v, c[nt][3] + b2v);
        }
    }
    __syncthreads();

    // ---- CPB bias: two MLP layers on bf16 HMMA, accumulate into logits ----
    const uint4* W1v4 = (const uint4*)W1v;
    const unsigned ONE_PACK = 0x00003F80u;   // pack_bf16(1.0f, 0.0f)
    int pbase = w*256;
    for (int mt = 0; mt < 16; mt++) {
        int p0 = pbase + mt*16 + g;
        int p1 = p0 + 8;
        unsigned pf0 = pf[p0], pf1 = pf[p1];
        unsigned af0 = (tig == 0) ? pf0 : (tig == 1) ? ONE_PACK : 0u;
        unsigned af1 = (tig == 0) ? pf1 : (tig == 1) ? ONE_PACK : 0u;

        float hc[8][4];
        #pragma unroll
        for (int nt = 0; nt < 8; nt++) {
            hc[nt][0] = hc[nt][1] = hc[nt][2] = hc[nt][3] = 0.f;
            mma_bf16(hc[nt][0], hc[nt][1], hc[nt][2], hc[nt][3],
                     af0, af1, 0u, 0u, w0b[nt], 0u);
        }
        unsigned a[4][4];
        #pragma unroll
        for (int kt = 0; kt < 4; kt++) {
            a[kt][0] = pack_bf16(fmaxf(hc[2*kt][0], 0.f),   fmaxf(hc[2*kt][1], 0.f));
            a[kt][1] = pack_bf16(fmaxf(hc[2*kt][2], 0.f),   fmaxf(hc[2*kt][3], 0.f));
            a[kt][2] = pack_bf16(fmaxf(hc[2*kt+1][0], 0.f), fmaxf(hc[2*kt+1][1], 0.f));
            a[kt][3] = pack_bf16(fmaxf(hc[2*kt+1][2], 0.f), fmaxf(hc[2*kt+1][3], 0.f));
        }

        float acc0 = 0.f, acc1 = 0.f;
        #pragma unroll
        for (int nt = 0; nt < 8; nt++) {
            uint4 u0 = W1v4[l*17 + nt*2];
            uint4 u1 = W1v4[l*17 + nt*2 + 1];
            float c0 = 0.f, c1 = 0.f, c2 = 0.f, c3 = 0.f;
            mma_bf16(c0, c1, c2, c3, a[0][0], a[0][1], a[0][2], a[0][3], u0.x, u0.y);
            mma_bf16(c0, c1, c2, c3, a[1][0], a[1][1], a[1][2], a[1][3], u0.z, u0.w);
            mma_bf16(c0, c1, c2, c3, a[2][0], a[2][1], a[2][2], a[2][3], u1.x, u1.y);
            mma_bf16(c0, c1, c2, c3, a[3][0], a[3][1], a[3][2], a[3][3], u1.z, u1.w);
            int col0 = nt*8 + 2*tig;
            float2 b1v = *(const float2*)&b1s[col0];
            float2 w2v = *(const float2*)&w2s[col0];
            acc0 += fmaxf(c0 + b1v.x, 0.f)*w2v.x + fmaxf(c1 + b1v.y, 0.f)*w2v.y;
            acc1 += fmaxf(c2 + b1v.x, 0.f)*w2v.x + fmaxf(c3 + b1v.y, 0.f)*w2v.y;
        }
        acc0 += __shfl_xor_sync(0xffffffffu, acc0, 1);
        acc0 += __shfl_xor_sync(0xffffffffu, acc0, 2);
        acc1 += __shfl_xor_sync(0xffffffffu, acc1, 1);
        acc1 += __shfl_xor_sync(0xffffffffu, acc1, 2);
        if (tig == 0) {
            logits[(p0 >> 6)*68 + (p0 & 63)] += acc0;
            logits[(p1 >> 6)*68 + (p1 & 63)] += acc1;
        }
    }
    __syncthreads();

    // ---- softmax over j=64 per row ----
    for (int rr = 0; rr < 4; rr++) {
        int row = w*4 + rr;
        float l0 = logits[row*68 + l], l1 = logits[row*68 + 32 + l];
        float m = fmaxf(l0, l1);
        #pragma unroll
        for (int o = 16; o; o >>= 1) m = fmaxf(m, __shfl_xor_sync(0xffffffffu, m, o));
        float e0 = __expf(l0 - m), e1 = __expf(l1 - m);
        float ss = e0 + e1;
        #pragma unroll
        for (int o = 16; o; o >>= 1) ss += __shfl_xor_sync(0xffffffffu, ss, o);
        float inv = 1.f / ss;
        logits[row*68 + l] = e0*inv;
        logits[row*68 + 32 + l] = e1*inv;
    }
    __syncthreads();

    // ---- attn @ v via tf32 mma; warp w: rows (w&1)*16.., d-cols (w>>1)*8.. ----
    {
        int mw2 = (w & 1) * 16, n0v = (w >> 1) * 8;
        float c0 = 0.f, c1 = 0.f, c2 = 0.f, c3 = 0.f;
        #pragma unroll
        for (int kk = 0; kk < 64; kk += 8) {
            unsigned a0 = f2tf32(logits[(mw2 + g)*68 + kk + tig]);
            unsigned a1 = f2tf32(logits[(mw2 + g + 8)*68 + kk + tig]);
            unsigned a2 = f2tf32(logits[(mw2 + g)*68 + kk + tig + 4]);
            unsigned a3 = f2tf32(logits[(mw2 + g + 8)*68 + kk + tig + 4]);
            unsigned b0 = f2tf32(vs[(kk + tig)*36 + n0v + g]);
            unsigned b1 = f2tf32(vs[(kk + tig + 4)*36 + n0v + g]);
            mma_tf32(c0, c1, c2, c3, a0, a1, a2, a3, b0, b1);
        }
        int col = h*32 + n0v + 2*tig;
        *(float2*)&g_attn[(b*1024 + i0 + mw2 + g)*256 + col]     = make_float2(c0, c1);
        *(float2*)&g_attn[(b*1024 + i0 + mw2 + g + 8)*256 + col] = make_float2(c2, c3);
    }
}

// ---------------- tf32 tensor-core GEMM, 128x64 tiles, pipelined ----------------
// A: MxK row-major. BT=false: B is KxN. BT=true: B is NxK (C = A @ B^T).
// EPI 0: C = acc + bias[col] + res[row,col] ; EPI 1: C = relu(acc + bias[col])
template<bool BT, int EPI>
__global__ __launch_bounds__(256) void gemm_tf32(
        const float* __restrict__ A, const float* __restrict__ B,
        const float* __restrict__ bias, const float* __restrict__ res,
        float* __restrict__ C, int M, int N, int K) {
    const int m0 = blockIdx.y * 128, n0 = blockIdx.x * 64;
    __shared__ __align__(16) unsigned As[128*20];
    __shared__ __align__(16) unsigned Bs[64*20];    // n-major: Bs[n][k]
    int t = threadIdx.x, w = t >> 5, l = t & 31, g = l >> 2, ti = l & 3;
    int mw = (w & 3) * 32, nw = (w >> 2) * 32;

    float c[2][4][4];
    #pragma unroll
    for (int mt = 0; mt < 2; mt++)
        #pragma unroll
        for (int nt = 0; nt < 4; nt++)
            c[mt][nt][0] = c[mt][nt][1] = c[mt][nt][2] = c[mt][nt][3] = 0.f;

    int ra = t >> 1, ca = (t & 1) * 8;
    int rb, cb;
    if (BT) { rb = t >> 2; cb = (t & 3) * 4; }
    else    { rb = t >> 4; cb = (t & 15) * 4; }

    float4 pa0, pa1, pb;
    pa0 = *(const float4*)&A[(m0 + ra)*K + ca];
    pa1 = *(const float4*)&A[(m0 + ra)*K + ca + 4];
    if (BT) pb = *(const float4*)&B[(n0 + rb)*K + cb];
    else    pb = *(const float4*)&B[rb*N + n0 + cb];

    for (int k0 = 0; k0 < K; k0 += 16) {
        *(uint4*)&As[ra*20 + ca]     = make_uint4(f2tf32(pa0.x), f2tf32(pa0.y), f2tf32(pa0.z), f2tf32(pa0.w));
        *(uint4*)&As[ra*20 + ca + 4] = make_uint4(f2tf32(pa1.x), f2tf32(pa1.y), f2tf32(pa1.z), f2tf32(pa1.w));
        if (BT) {
            *(uint4*)&Bs[rb*20 + cb] = make_uint4(f2tf32(pb.x), f2tf32(pb.y), f2tf32(pb.z), f2tf32(pb.w));
        } else {
            Bs[(cb+0)*20 + rb] = f2tf32(pb.x);
            Bs[(cb+1)*20 + rb] = f2tf32(pb.y);
            Bs[(cb+2)*20 + rb] = f2tf32(pb.z);
            Bs[(cb+3)*20 + rb] = f2tf32(pb.w);
        }
        __syncthreads();
        if (k0 + 16 < K) {
            pa0 = *(const float4*)&A[(m0 + ra)*K + k0 + 16 + ca];
            pa1 = *(const float4*)&A[(m0 + ra)*K + k0 + 16 + ca + 4];
            if (BT) pb = *(const float4*)&B[(n0 + rb)*K + k0 + 16 + cb];
            else    pb = *(const float4*)&B[(k0 + 16 + rb)*N + n0 + cb];
        }
        #pragma unroll
        for (int kk = 0; kk < 16; kk += 8) {
            unsigned a[2][4];
            #pragma unroll
            for (int mt = 0; mt < 2; mt++) {
                int r = mw + mt*16 + g;
                a[mt][0] = As[r*20 + kk + ti];
                a[mt][1] = As[(r + 8)*20 + kk + ti];
                a[mt][2] = As[r*20 + kk + ti + 4];
                a[mt][3] = As[(r + 8)*20 + kk + ti + 4];
            }
            #pragma unroll
            for (int nt = 0; nt < 4; nt++) {
                int nc = nw + nt*8 + g;
                unsigned b0 = Bs[nc*20 + kk + ti];
                unsigned b1 = Bs[nc*20 + kk + ti + 4];
                #pragma unroll
                for (int mt = 0; mt < 2; mt++)
                    mma_tf32(c[mt][nt][0], c[mt][nt][1], c[mt][nt][2], c[mt][nt][3],
                             a[mt][0], a[mt][1], a[mt][2], a[mt][3], b0, b1);
            }
        }
        __syncthreads();
    }
    #pragma unroll
    for (int mt = 0; mt < 2; mt++) {
        #pragma unroll
        for (int nt = 0; nt < 4; nt++) {
            int col = n0 + nw + nt*8 + 2*ti;
            int r0 = m0 + mw + mt*16 + g, r1 = r0 + 8;
            float2 bi = *(const float2*)&bias[col];
            float2 v0 = make_float2(c[mt][nt][0] + bi.x, c[mt][nt][1] + bi.y);
            float2 v1 = make_float2(c[mt][nt][2] + bi.x, c[mt][nt][3] + bi.y);
            if (EPI == 1) {
                v0.x = fmaxf(v0.x, 0.f); v0.y = fmaxf(v0.y, 0.f);
                v1.x = fmaxf(v1.x, 0.f); v1.y = fmaxf(v1.y, 0.f);
            } else {
                float2 r0v = *(const float2*)&res[r0*N + col];
                float2 r1v = *(const float2*)&res[r1*N + col];
                v0.x += r0v.x; v0.y += r0v.y;
                v1.x += r1v.x; v1.y += r1v.y;
            }
            *(float2*)&C[r0*N + col] = v0;
            *(float2*)&C[r1*N + col] = v1;
        }
    }
}

// ---------------- launcher ----------------
extern "C" void kernel_launch(void* const* d_in, const int* in_sizes, int n_in,
                              void* d_out, int out_size) {
    const float* src     = (const float*)d_in[0];
    const float* norm1_g = (const float*)d_in[1];
    const float* norm1_b = (const float*)d_in[2];
    const float* wq      = (const float*)d_in[3];
    const float* wdw     = (const float*)d_in[4];
    const float* bdw     = (const float*)d_in[5];
    const float* woff    = (const float*)d_in[6];
    const float* wk      = (const float*)d_in[7];
    const float* wv      = (const float*)d_in[8];
    const float* cpb_w0  = (const float*)d_in[9];
    const float* cpb_b0  = (const float*)d_in[10];
    const float* cpb_w1  = (const float*)d_in[11];
    const float* cpb_b1  = (const float*)d_in[12];
    const float* cpb_w2  = (const float*)d_in[13];
    const float* cpb_b2  = (const float*)d_in[14];
    const float* wout    = (const float*)d_in[15];
    const float* bout    = (const float*)d_in[16];
    const float* norm2_g = (const float*)d_in[17];
    const float* norm2_b = (const float*)d_in[18];
    const float* ffn_w1  = (const float*)d_in[19];
    const float* ffn_b1  = (const float*)d_in[20];
    const float* ffn_w2  = (const float*)d_in[21];
    const float* ffn_b2  = (const float*)d_in[22];

    void *p_x, *p_attn, *p_srcp, *p_src2, *p_ffnh;
    cudaGetSymbolAddress(&p_x,    g_x);
    cudaGetSymbolAddress(&p_attn, g_attn);
    cudaGetSymbolAddress(&p_srcp, g_srcp);
    cudaGetSymbolAddress(&p_src2, g_src2);
    cudaGetSymbolAddress(&p_ffnh, g_ffnh);

    ln_kernel<<<2048, 256>>>(src, norm1_g, norm1_b, (float*)p_x, 1);
    qproj_kernel<<<dim3(16, 8), 256>>>(wq);
    offset_sample_kv_kernel<<<16, 256>>>(wdw, bdw, woff, wk, wv);
    attn_kernel<<<dim3(32, 16), 256>>>(cpb_w0, cpb_b0, cpb_w1, cpb_b1, cpb_w2, cpb_b2);
    gemm_tf32<true, 0><<<dim3(4, 16), 256>>>((const float*)p_attn, wout, bout, src,
                                             (float*)p_srcp, 2048, 256, 256);
    ln_kernel<<<2048, 256>>>((const float*)p_srcp, norm2_g, norm2_b, (float*)p_src2, 0);
    gemm_tf32<false, 1><<<dim3(16, 16), 256>>>((const float*)p_src2, ffn_w1, ffn_b1, nullptr,
                                               (float*)p_ffnh, 2048, 1024, 256);
    gemm_tf32<false, 0><<<dim3(4, 16), 256>>>((const float*)p_ffnh, ffn_w2, ffn_b2,
                                              (const float*)p_srcp, (float*)d_out,
                                              2048, 256, 1024);
}